// round 13
// baseline (speedup 1.0000x reference)
#include <cuda_runtime.h>

#define T_STEPS 750
#define B_TOT   1024
#define HID     100
#define KDIM    104      // 100 recurrent + 4 input-drive rows
#define BT      4        // batch per tile; CTA = 2 tiles = 8 batch
#define NTHREADS 128
#define NBLOCKS (B_TOT / (2 * BT))   // 128 CTAs, 1 per SM
#define ALPHA   0.01f
#define NSTD    0.1f

__device__ __forceinline__ float tanh_fast(float x) {
    float y;
    asm("tanh.approx.f32 %0, %1;" : "=f"(y) : "f"(x));
    return y;
}
__device__ __forceinline__ unsigned long long pack2(float x) {
    unsigned long long r;
    asm("mov.b64 %0, {%1, %1};" : "=l"(r) : "f"(x));
    return r;
}
__device__ __forceinline__ void ffma2(unsigned long long& d,
                                      unsigned long long a,
                                      unsigned long long b) {
    asm("fma.rn.f32x2 %0, %1, %2, %0;" : "+l"(d) : "l"(a), "l"(b));
}
__device__ __forceinline__ unsigned long long fadd2(unsigned long long a,
                                                    unsigned long long b) {
    unsigned long long r;
    asm("add.rn.f32x2 %0, %1, %2;" : "=l"(r) : "l"(a), "l"(b));
    return r;
}
__device__ __forceinline__ float2 unpack2(unsigned long long v) {
    float2 f;
    asm("mov.b64 {%0, %1}, %2;" : "=f"(f.x), "=f"(f.y) : "l"(v));
    return f;
}

// One interval: barrier; publish OTHER tile's R (from its current x) into
// Rpub; prefetch THIS tile's next noise/u; consume Rcons (R5 FFMA2 loop);
// update THIS tile's x.  The publish/prefetch stream is independent of the
// consume stream -> single-warp ILP fills the LDS/chain gaps.
__device__ __forceinline__ void interval(
    int tcur, int i, int b0_this,
    float (&x_this)[BT], const float (&x_other)[BT],
    const float (&Jreg)[KDIM], float ci,
    const float (&ncur)[BT], float (&nnext)[BT],
    float& unext, float upub,
    float (&Rcons)[KDIM][BT], float (&Rpub)[KDIM][BT],
    const float* __restrict__ noise,
    const float* __restrict__ input_seq)
{
    __syncthreads();   // sole barrier: separates Rpub's prior reads from its
                       // writes here, and Rcons's writes (last interval) from
                       // its reads here.

    // ---- publish other tile's operands (r = tanh(x_other), u) ----
    if (i < HID) {
        float4 r;
        r.x = tanh_fast(x_other[0]); r.y = tanh_fast(x_other[1]);
        r.z = tanh_fast(x_other[2]); r.w = tanh_fast(x_other[3]);
        *(float4*)&Rpub[i][0] = r;
    }
    if (i < 16) Rpub[HID + (i & 3)][i >> 2] = upub;   // b = i>>2, c = i&3

    // ---- prefetch this tile's next-step noise + u (2-interval lead) ----
    const int tn = (tcur + 1 < T_STEPS) ? (tcur + 1) : tcur;
    {
        const float* np = noise + ((size_t)tn * B_TOT + b0_this) * HID + i;
#pragma unroll
        for (int b = 0; b < BT; b++)
            nnext[b] = (i < HID) ? np[b * HID] : 0.0f;
        if (i < 16)
            unext = input_seq[((size_t)tn * B_TOT + b0_this + (i >> 2)) * 4 + (i & 3)];
    }

    // ---- consume: y[b] = sum_j Jreg[j] * Rcons[j][b]  (R5 loop verbatim) ----
    unsigned long long ya0 = 0ull, ya1 = 0ull, yb0 = 0ull, yb1 = 0ull;
#pragma unroll
    for (int j = 0; j < KDIM; j += 2) {
        ulonglong2 ra = *(const ulonglong2*)&Rcons[j][0];
        ulonglong2 rb = *(const ulonglong2*)&Rcons[j + 1][0];
        unsigned long long ja = pack2(Jreg[j]);
        unsigned long long jb = pack2(Jreg[j + 1]);
        ffma2(ya0, ra.x, ja);
        ffma2(ya1, ra.y, ja);
        ffma2(yb0, rb.x, jb);
        ffma2(yb1, rb.y, jb);
    }
    unsigned long long y01 = fadd2(ya0, yb0);
    unsigned long long y23 = fadd2(ya1, yb1);

    // ---- update x_this ----
    float2 f01 = unpack2(y01), f23 = unpack2(y23);
    float y[BT] = { f01.x, f01.y, f23.x, f23.y };
#pragma unroll
    for (int b = 0; b < BT; b++) {
        x_this[b] = fmaf(1.0f - ALPHA, x_this[b],
                    fmaf(ALPHA, y[b],
                    fmaf(ALPHA * NSTD, ncur[b], ci)));
    }
}

__global__ void __launch_bounds__(NTHREADS, 1)
rnn_kernel(const float* __restrict__ input_seq,
           const float* __restrict__ noise,
           const float* __restrict__ J_w,
           const float* __restrict__ Bmat,
           const float* __restrict__ c_x,
           const float* __restrict__ Wout_w,
           const float* __restrict__ Wout_b,
           float* __restrict__ out)
{
    __shared__ __align__(16) float RA[KDIM][BT];   // tile A operand buffer
    __shared__ __align__(16) float RB[KDIM][BT];   // tile B operand buffer
    __shared__ float warp_part[4][2 * BT];         // epilogue partials

    const int i   = threadIdx.x;            // state row owned by this thread
    const int b0A = blockIdx.x * (2 * BT);  // tile A batch base
    const int b0B = b0A + BT;               // tile B batch base

    // Row i of [J ; Bmat^T] held permanently in registers.
    float Jreg[KDIM];
#pragma unroll
    for (int j = 0; j < KDIM; j++) {
        float v = 0.0f;
        if (i < HID)
            v = (j < HID) ? J_w[i * HID + j] : Bmat[(j - HID) * HID + i];
        Jreg[j] = v;
    }
    const float ci = (i < HID) ? (ALPHA * c_x[i]) : 0.0f;

    float xA[BT], xB[BT];
#pragma unroll
    for (int b = 0; b < BT; b++) { xA[b] = 0.0f; xB[b] = 0.0f; }

    // Noise/u double buffers per tile (parity = step & 1).
    float nA0[BT], nA1[BT], nB0[BT], nB1[BT];
    float uA0 = 0.0f, uA1 = 0.0f, uB0 = 0.0f, uB1 = 0.0f;

    // ---- Prologue ----
    {
        const float* npA = noise + (size_t)b0A * HID + i;
        const float* npB = noise + (size_t)b0B * HID + i;
#pragma unroll
        for (int b = 0; b < BT; b++) {
            nA0[b] = (i < HID) ? npA[b * HID] : 0.0f;
            nB0[b] = (i < HID) ? npB[b * HID] : 0.0f;
        }
        if (i < 16) {
            uA0 = input_seq[((size_t)b0A + (i >> 2)) * 4 + (i & 3)];
            uB0 = input_seq[((size_t)b0B + (i >> 2)) * 4 + (i & 3)];
        }
        // Publish R_A(0): r = tanh(0) = 0, u = u_A(0).
        if (i < HID) {
            float4 z = make_float4(0.f, 0.f, 0.f, 0.f);
            *(float4*)&RA[i][0] = z;
        }
        if (i < 16) RA[HID + (i & 3)][i >> 2] = uA0;
    }

    // ---- Main scan: 2 steps (4 intervals) per iteration, static parity ----
    // A-interval(m): consume RA(m), update xA w/ nA[par]; publish RB(m)
    //   [tanh(xB(m)), uB[par]]; prefetch nA[1-par] <- noise_A(m+1), uA[1-par].
    // B-interval(m): consume RB(m), update xB w/ nB[par]; publish RA(m+1)
    //   [tanh(xA(m+1)), uA[1-par]]; prefetch nB[1-par], uB[1-par].
    for (int m = 0; m < T_STEPS; m += 2) {
        // m, parity 0
        interval(m, i, b0A, xA, xB, Jreg, ci, nA0, nA1, uA1, uB0,
                 RA, RB, noise, input_seq);
        interval(m, i, b0B, xB, xA, Jreg, ci, nB0, nB1, uB1, uA1,
                 RB, RA, noise, input_seq);
        // m+1, parity 1
        interval(m + 1, i, b0A, xA, xB, Jreg, ci, nA1, nA0, uA0, uB1,
                 RA, RB, noise, input_seq);
        interval(m + 1, i, b0B, xB, xA, Jreg, ci, nB1, nB0, uB0, uA0,
                 RB, RA, noise, input_seq);
    }

    // ---- Epilogue: out[b] = tanh(x_final) . Wout + bias (deterministic) ----
    {
        const float w = (i < HID) ? Wout_w[i] : 0.0f;
        float part[2 * BT];
#pragma unroll
        for (int b = 0; b < BT; b++) {
            part[b]      = (i < HID) ? w * tanhf(xA[b]) : 0.0f;
            part[BT + b] = (i < HID) ? w * tanhf(xB[b]) : 0.0f;
        }
#pragma unroll
        for (int off = 16; off > 0; off >>= 1) {
#pragma unroll
            for (int b = 0; b < 2 * BT; b++)
                part[b] += __shfl_xor_sync(0xFFFFFFFFu, part[b], off);
        }
        const int warp = i >> 5;
        if ((i & 31) == 0) {
#pragma unroll
            for (int b = 0; b < 2 * BT; b++)
                warp_part[warp][b] = part[b];
        }
        __syncthreads();
        if (i < 2 * BT) {
            float s = warp_part[0][i] + warp_part[1][i]
                    + warp_part[2][i] + warp_part[3][i];
            out[b0A + i] = s + Wout_b[0];
        }
    }
}

extern "C" void kernel_launch(void* const* d_in, const int* in_sizes, int n_in,
                              void* d_out, int out_size)
{
    const float* input_seq = (const float*)d_in[0];  // [750,1024,4]
    const float* noise     = (const float*)d_in[1];  // [750,1024,100]
    const float* J_w       = (const float*)d_in[2];  // [100,100]
    const float* Bmat      = (const float*)d_in[3];  // [4,100]
    const float* c_x       = (const float*)d_in[4];  // [100]
    const float* Wout_w    = (const float*)d_in[5];  // [1,100]
    const float* Wout_b    = (const float*)d_in[6];  // [1]
    float* out = (float*)d_out;                      // [1024]

    rnn_kernel<<<NBLOCKS, NTHREADS>>>(
        input_seq, noise, J_w, Bmat, c_x, Wout_w, Wout_b, out);
}

// round 14
// speedup vs baseline: 1.2666x; 1.2666x over previous
#include <cuda_runtime.h>

#define T_STEPS 750
#define B_TOT   1024
#define HID     100
#define KDIM    104      // 100 recurrent + 4 input-drive rows
#define BTILE   2
#define NTHREADS 128
#define NBLOCKS (B_TOT / BTILE)   // 512 CTAs -> 4 CTAs/SM, 4 barrier domains
#define ALPHA   0.01f
#define NSTD    0.1f

__device__ __forceinline__ float tanh_fast(float x) {
    float y;
    asm("tanh.approx.f32 %0, %1;" : "=f"(y) : "f"(x));
    return y;
}
__device__ __forceinline__ unsigned long long pack2(float x) {
    unsigned long long r;
    asm("mov.b64 %0, {%1, %1};" : "=l"(r) : "f"(x));
    return r;
}
__device__ __forceinline__ void ffma2(unsigned long long& d,
                                      unsigned long long a,
                                      unsigned long long b) {
    asm("fma.rn.f32x2 %0, %1, %2, %0;" : "+l"(d) : "l"(a), "l"(b));
}
__device__ __forceinline__ unsigned long long fadd2(unsigned long long a,
                                                    unsigned long long b) {
    unsigned long long r;
    asm("add.rn.f32x2 %0, %1, %2;" : "=l"(r) : "l"(a), "l"(b));
    return r;
}
__device__ __forceinline__ float2 unpack2(unsigned long long v) {
    float2 f;
    asm("mov.b64 {%0, %1}, %2;" : "=f"(f.x), "=f"(f.y) : "l"(v));
    return f;
}

// One RNN step (R5 structure, BTILE=2).  R rows are 8 bytes; one uniform
// LDS.128 per even j yields (R[j][0], R[j][1], R[j+1][0], R[j+1][1]).
__device__ __forceinline__ void rnn_step(
    int tcur, int i, int b0,
    float (&x)[BTILE], const float (&Jreg)[KDIM], float ci,
    const float (&ncur)[BTILE], float ucur,
    float (&nnext)[BTILE], float& unext,
    float (&R)[KDIM][BTILE],
    const float* __restrict__ noise,
    const float* __restrict__ input_seq)
{
    // Phase 1: publish r rows (i < 100) and u rows (100..103, lanes 0..7)
    if (i < HID) {
        float2 r0;
        r0.x = tanh_fast(x[0]);
        r0.y = tanh_fast(x[1]);
        *(float2*)&R[i][0] = r0;
    }
    if (i < 8) R[HID + (i & 3)][i >> 2] = ucur;   // b = i>>2, c = i&3
    __syncthreads();

    // Prefetch next step's noise + input (one full step ahead of use)
    const int tn = (tcur + 1 < T_STEPS) ? (tcur + 1) : tcur;
    {
        const float* np = noise + ((size_t)tn * B_TOT + b0) * HID + i;
#pragma unroll
        for (int b = 0; b < BTILE; b++)
            nnext[b] = (i < HID) ? np[b * HID] : 0.0f;
        if (i < 8)
            unext = input_seq[((size_t)tn * B_TOT + b0 + (i >> 2)) * 4 + (i & 3)];
    }

    // Phase 2: y[b] = sum_j Jreg[j] * R[j][b]  (2 packed accs, even/odd j)
    unsigned long long ya = 0ull, yb = 0ull;
#pragma unroll
    for (int j = 0; j < KDIM; j += 2) {
        ulonglong2 rr = *(const ulonglong2*)&R[j][0];
        ffma2(ya, rr.x, pack2(Jreg[j]));
        ffma2(yb, rr.y, pack2(Jreg[j + 1]));
    }
    __syncthreads();   // all reads of R done before next step overwrites it

    unsigned long long y01 = fadd2(ya, yb);

    // Phase 3: x <- (1-a)x + a*y + a*c + (a*noise_std)*n   (registers only)
    float2 f01 = unpack2(y01);
    float y[BTILE] = { f01.x, f01.y };
#pragma unroll
    for (int b = 0; b < BTILE; b++) {
        x[b] = fmaf(1.0f - ALPHA, x[b],
               fmaf(ALPHA, y[b],
               fmaf(ALPHA * NSTD, ncur[b], ci)));
    }
}

__global__ void __launch_bounds__(NTHREADS, 4)
rnn_kernel(const float* __restrict__ input_seq,
           const float* __restrict__ noise,
           const float* __restrict__ J_w,
           const float* __restrict__ Bmat,
           const float* __restrict__ c_x,
           const float* __restrict__ Wout_w,
           const float* __restrict__ Wout_b,
           float* __restrict__ out)
{
    __shared__ __align__(16) float R[KDIM][BTILE];
    __shared__ float warp_part[4][BTILE];   // epilogue partials

    const int i  = threadIdx.x;            // state row owned by this thread
    const int b0 = blockIdx.x * BTILE;     // batch slice base

    // Row i of [J ; Bmat^T] held permanently in registers (static indexing).
    float Jreg[KDIM];
#pragma unroll
    for (int j = 0; j < KDIM; j++) {
        float v = 0.0f;
        if (i < HID)
            v = (j < HID) ? J_w[i * HID + j] : Bmat[(j - HID) * HID + i];
        Jreg[j] = v;
    }
    const float ci = (i < HID) ? (ALPHA * c_x[i]) : 0.0f;

    float x[BTILE];
#pragma unroll
    for (int b = 0; b < BTILE; b++) x[b] = 0.0f;

    // Preload t=0 noise + input into buffer A
    float nA[BTILE], nB[BTILE];
    float uA = 0.0f, uB = 0.0f;
    {
        const float* np = noise + (size_t)b0 * HID + i;
#pragma unroll
        for (int b = 0; b < BTILE; b++)
            nA[b] = (i < HID) ? np[b * HID] : 0.0f;
        if (i < 8)
            uA = input_seq[((size_t)b0 + (i >> 2)) * 4 + (i & 3)];
    }

    // Main scan, unrolled by 2 for register double-buffering of noise/input
    for (int t = 0; t < T_STEPS; t += 2) {
        rnn_step(t,     i, b0, x, Jreg, ci, nA, uA, nB, uB, R, noise, input_seq);
        rnn_step(t + 1, i, b0, x, Jreg, ci, nB, uB, nA, uA, R, noise, input_seq);
    }

    // Epilogue: out[b] = tanh(x_final[b]) . Wout + bias.
    // Deterministic: butterfly shuffle within warp, fixed-order cross-warp sum.
    {
        const float w = (i < HID) ? Wout_w[i] : 0.0f;
        float part[BTILE];
#pragma unroll
        for (int b = 0; b < BTILE; b++)
            part[b] = (i < HID) ? w * tanhf(x[b]) : 0.0f;
#pragma unroll
        for (int off = 16; off > 0; off >>= 1) {
#pragma unroll
            for (int b = 0; b < BTILE; b++)
                part[b] += __shfl_xor_sync(0xFFFFFFFFu, part[b], off);
        }
        const int warp = i >> 5;
        if ((i & 31) == 0) {
#pragma unroll
            for (int b = 0; b < BTILE; b++)
                warp_part[warp][b] = part[b];
        }
        __syncthreads();
        if (i < BTILE) {
            float s = warp_part[0][i] + warp_part[1][i]
                    + warp_part[2][i] + warp_part[3][i];
            out[b0 + i] = s + Wout_b[0];
        }
    }
}

extern "C" void kernel_launch(void* const* d_in, const int* in_sizes, int n_in,
                              void* d_out, int out_size)
{
    const float* input_seq = (const float*)d_in[0];  // [750,1024,4]
    const float* noise     = (const float*)d_in[1];  // [750,1024,100]
    const float* J_w       = (const float*)d_in[2];  // [100,100]
    const float* Bmat      = (const float*)d_in[3];  // [4,100]
    const float* c_x       = (const float*)d_in[4];  // [100]
    const float* Wout_w    = (const float*)d_in[5];  // [1,100]
    const float* Wout_b    = (const float*)d_in[6];  // [1]
    float* out = (float*)d_out;                      // [1024]

    rnn_kernel<<<NBLOCKS, NTHREADS>>>(
        input_seq, noise, J_w, Bmat, c_x, Wout_w, Wout_b, out);
}